// round 1
// baseline (speedup 1.0000x reference)
#include <cuda_runtime.h>
#include <cstdint>

#define BDIM 32
#define PDIM 1024
#define VDIM 100
#define EDIM 512
#define HDIM 512
#define EPSV 1e-5f
#define MAXF 9216   // max possible total frames = 1024 * 9

// ---------------- scratch (static device globals; no allocation) ----------------
__device__ float g_W1t[3 * EDIM * HDIM];            // [k][e][h]  (3 MB)
__device__ float g_Atab[3 * VDIM * HDIM];           // [k][v][h]  (600 KB)
__device__ float g_c1[HDIM];
__device__ float g_c2[HDIM];
__device__ float g_W2t[3 * HDIM * HDIM];            // [k][h'][h] scale-folded (3 MB)
__device__ float g_y1[(size_t)BDIM * HDIM * PDIM];  // 64 MB, [b][h][p]
__device__ float g_y2[(size_t)BDIM * HDIM * PDIM];  // 64 MB, [b][h][p]
__device__ int   g_fidx[BDIM * MAXF];               // frame -> phoneme index, -1 = masked

// ---------------- prep: fold BN into bias vectors ----------------
__global__ void k_prep_vec(const float* b1, const float* g1, const float* be1,
                           const float* m1, const float* v1,
                           const float* b2, const float* g2, const float* be2,
                           const float* m2, const float* v2) {
    int h = threadIdx.x;
    if (h < HDIM) {
        float s1 = g1[h] * rsqrtf(v1[h] + EPSV);
        g_c1[h] = b1[h] * s1 + be1[h] - m1[h] * s1;
        float s2 = g2[h] * rsqrtf(v2[h] + EPSV);
        g_c2[h] = b2[h] * s2 + be2[h] - m2[h] * s2;
    }
}

// ---------------- prep: transpose conv1_w (H,E,3) -> [k][e][h] ----------------
__global__ void k_w1t(const float* __restrict__ w1) {
    int idx = blockIdx.x * blockDim.x + threadIdx.x;
    if (idx >= 3 * EDIM * HDIM) return;
    int h = idx / (EDIM * 3);
    int r = idx % (EDIM * 3);
    int e = r / 3;
    int k = r % 3;
    g_W1t[(k * EDIM + e) * HDIM + h] = w1[idx];
}

// ---------------- prep: Atab[k][v][h] = scale1[h] * sum_e emb[v,e]*W1[h,e,k] ----------------
__global__ void k_atab(const float* __restrict__ emb,
                       const float* __restrict__ g1, const float* __restrict__ v1) {
    int v = blockIdx.x;
    int k = blockIdx.y;
    int h = threadIdx.x;   // 512 threads
    __shared__ float es[EDIM];
    es[h] = emb[v * EDIM + h];
    __syncthreads();
    const float* w = g_W1t + (size_t)k * EDIM * HDIM + h;
    float acc = 0.f;
#pragma unroll 8
    for (int e = 0; e < EDIM; ++e)
        acc += es[e] * w[(size_t)e * HDIM];
    float scale = g1[h] * rsqrtf(v1[h] + EPSV);
    g_Atab[((size_t)k * VDIM + v) * HDIM + h] = acc * scale;
}

// ---------------- prep: W2t[k][h'][h] = scale2[h]*W2[h,h',k] ----------------
__global__ void k_w2t(const float* __restrict__ w2,
                      const float* __restrict__ g2, const float* __restrict__ v2) {
    int idx = blockIdx.x * blockDim.x + threadIdx.x;
    if (idx >= 3 * HDIM * HDIM) return;
    int h = idx / (HDIM * 3);
    int r = idx % (HDIM * 3);
    int hp = r / 3;
    int k = r % 3;
    float s2 = g2[h] * rsqrtf(v2[h] + EPSV);
    g_W2t[((size_t)k * HDIM + hp) * HDIM + h] = w2[idx] * s2;
}

// ---------------- stage 1: y1 via table lookups (conv1+BN+ReLU collapsed) ----------------
__global__ void k_y1(const int* __restrict__ ids) {
    __shared__ float s[HDIM][17];
    __shared__ int sid[18];
    int b = blockIdx.x;
    int p0 = blockIdx.y * 16;
    int tid = threadIdx.x;   // 256
    if (tid < 18) {
        int q = p0 - 1 + tid;
        sid[tid] = (q >= 0 && q < PDIM) ? ids[b * PDIM + q] : -1;
    }
    __syncthreads();
    for (int h = tid; h < HDIM; h += 256) {
        float cc = g_c1[h];
#pragma unroll
        for (int pl = 0; pl < 16; ++pl) {
            int i0 = sid[pl], i1 = sid[pl + 1], i2 = sid[pl + 2];
            float v = cc;
            if (i0 >= 0) v += g_Atab[(0 * VDIM + i0) * HDIM + h];
            if (i1 >= 0) v += g_Atab[(1 * VDIM + i1) * HDIM + h];
            if (i2 >= 0) v += g_Atab[(2 * VDIM + i2) * HDIM + h];
            s[h][pl] = fmaxf(v, 0.f);
        }
    }
    __syncthreads();
    float* dst = g_y1 + (size_t)b * HDIM * PDIM + p0;
    for (int i = tid; i < HDIM * 16; i += 256) {
        int h = i >> 4, p = i & 15;
        dst[(size_t)h * PDIM + p] = s[h][p];
    }
}

// ---------------- stage 2: conv2 as GEMM (fp32 SIMT, 128x128x8 tile) ----------------
#define BM 128
#define BN 128
#define BK 8
__global__ __launch_bounds__(256, 2) void k_gemm() {
    int p0 = blockIdx.x * BN;
    int h0 = blockIdx.y * BM;
    int b = blockIdx.z;
    __shared__ float As[BK][BM];
    __shared__ float Bs[BK][BN];
    int tid = threadIdx.x;       // 256
    int tx = tid & 15;           // N dir
    int ty = tid >> 4;           // M dir
    float acc[8][8];
#pragma unroll
    for (int i = 0; i < 8; ++i)
#pragma unroll
        for (int j = 0; j < 8; ++j) acc[i][j] = 0.f;

    const float* y1b = g_y1 + (size_t)b * HDIM * PDIM;

    for (int tap = 0; tap < 3; ++tap) {
        const float* A = g_W2t + (size_t)tap * HDIM * HDIM;
        int shift = tap - 1;
        for (int kk = 0; kk < HDIM; kk += BK) {
            // load A tile: 1024 floats via float4
            {
                int idx = tid * 4;
                int r = idx >> 7, c = idx & 127;
                float4 v = *(const float4*)(A + (size_t)(kk + r) * HDIM + h0 + c);
                *(float4*)&As[r][c] = v;
            }
            // load B tile: scalar guarded (handles halo at batch edges)
#pragma unroll
            for (int i = 0; i < 4; ++i) {
                int idx = tid + i * 256;
                int r = idx >> 7, c = idx & 127;
                int gp = p0 + c + shift;
                Bs[r][c] = (gp >= 0 && gp < PDIM) ? y1b[(size_t)(kk + r) * PDIM + gp] : 0.f;
            }
            __syncthreads();
#pragma unroll
            for (int k = 0; k < BK; ++k) {
                float a[8], bb[8];
                *(float4*)(a)     = *(float4*)&As[k][ty * 8];
                *(float4*)(a + 4) = *(float4*)&As[k][ty * 8 + 4];
                *(float4*)(bb)     = *(float4*)&Bs[k][tx * 8];
                *(float4*)(bb + 4) = *(float4*)&Bs[k][tx * 8 + 4];
#pragma unroll
                for (int i = 0; i < 8; ++i)
#pragma unroll
                    for (int j = 0; j < 8; ++j) acc[i][j] += a[i] * bb[j];
            }
            __syncthreads();
        }
    }
    // epilogue: + folded bias, ReLU, store
#pragma unroll
    for (int i = 0; i < 8; ++i) {
        int h = h0 + ty * 8 + i;
        float cc = g_c2[h];
        float* dst = g_y2 + ((size_t)b * HDIM + h) * PDIM + p0 + tx * 8;
        float4 o0, o1;
        o0.x = fmaxf(acc[i][0] + cc, 0.f);
        o0.y = fmaxf(acc[i][1] + cc, 0.f);
        o0.z = fmaxf(acc[i][2] + cc, 0.f);
        o0.w = fmaxf(acc[i][3] + cc, 0.f);
        o1.x = fmaxf(acc[i][4] + cc, 0.f);
        o1.y = fmaxf(acc[i][5] + cc, 0.f);
        o1.z = fmaxf(acc[i][6] + cc, 0.f);
        o1.w = fmaxf(acc[i][7] + cc, 0.f);
        *(float4*)dst = o0;
        *(float4*)(dst + 4) = o1;
    }
}

// ---------------- stage 3: duration scan + frame->phoneme map ----------------
__global__ void k_scan(const int* __restrict__ durs, int F) {
    int b = blockIdx.x;
    int tid = threadIdx.x;   // 1024
    __shared__ int s[PDIM];
    int d = durs[b * PDIM + tid];
    s[tid] = d;
    __syncthreads();
    for (int off = 1; off < PDIM; off <<= 1) {
        int t = (tid >= off) ? s[tid - off] : 0;
        __syncthreads();
        s[tid] += t;
        __syncthreads();
    }
    int cum = s[tid];
    int total = s[PDIM - 1];
    int start = cum - d;
    for (int f = start; f < cum; ++f) g_fidx[b * MAXF + f] = tid;
    for (int f = total + tid; f < F; f += PDIM) g_fidx[b * MAXF + f] = -1;
}

// ---------------- stage 4: gather + mask to output ----------------
__global__ void k_gather(float* __restrict__ out, int F) {
    int bh = blockIdx.x;               // b*H + h
    int b = bh / HDIM;
    const float* row = g_y2 + (size_t)bh * PDIM;
    const int* fx = g_fidx + b * MAXF;
    float* o = out + (size_t)bh * F;
    for (int f = threadIdx.x; f < F; f += blockDim.x) {
        int ix = fx[f];
        o[f] = (ix >= 0) ? row[ix] : 0.f;
    }
}

// ---------------- launch ----------------
extern "C" void kernel_launch(void* const* d_in, const int* in_sizes, int n_in,
                              void* d_out, int out_size) {
    const int* ids   = (const int*)d_in[0];
    const int* durs  = (const int*)d_in[1];
    const float* emb = (const float*)d_in[2];
    const float* w1  = (const float*)d_in[3];
    const float* b1  = (const float*)d_in[4];
    const float* g1  = (const float*)d_in[5];
    const float* be1 = (const float*)d_in[6];
    const float* m1  = (const float*)d_in[7];
    const float* v1  = (const float*)d_in[8];
    const float* w2  = (const float*)d_in[9];
    const float* b2  = (const float*)d_in[10];
    const float* g2  = (const float*)d_in[11];
    const float* be2 = (const float*)d_in[12];
    const float* m2  = (const float*)d_in[13];
    const float* v2  = (const float*)d_in[14];
    float* out = (float*)d_out;
    int F = out_size / (BDIM * HDIM);

    k_prep_vec<<<1, 512>>>(b1, g1, be1, m1, v1, b2, g2, be2, m2, v2);
    k_w1t<<<(3 * EDIM * HDIM + 255) / 256, 256>>>(w1);
    k_atab<<<dim3(VDIM, 3), 512>>>(emb, g1, v1);
    k_w2t<<<(3 * HDIM * HDIM + 255) / 256, 256>>>(w2, g2, v2);
    k_y1<<<dim3(BDIM, PDIM / 16), 256>>>(ids);
    k_gemm<<<dim3(PDIM / BN, HDIM / BM, BDIM), 256>>>();
    k_scan<<<BDIM, PDIM>>>(durs, F);
    k_gather<<<BDIM * HDIM, 256>>>(out, F);
}

// round 5
// speedup vs baseline: 3.4387x; 3.4387x over previous
#include <cuda_runtime.h>
#include <cstdint>

#define BDIM 32
#define PDIM 1024
#define VDIM 100
#define EDIM 512
#define HDIM 512
#define EPSV 1e-5f
#define MAXF 9216
#define PPAD (PDIM + 2)

// GEMM tiling (mma.sync tf32, Ampere-style; no 'a'-arch features)
#define TM 128
#define TN 128
#define TK 32
#define NSTAGE 3
#define NCHUNK ((3 * HDIM) / TK)                 // 48
#define A_BYTES (TM * TK * 4)                    // 16384
#define B_BYTES (TN * TK * 4)                    // 16384
#define STAGE_BYTES (A_BYTES + B_BYTES)          // 32768
#define GEMM_SMEM (NSTAGE * STAGE_BYTES)         // 98304

// ---------------- scratch (static device globals) ----------------
__device__ float g_W1t[3 * EDIM * HDIM];            // [k][e][h]
__device__ float g_Atab[3 * VDIM * HDIM];           // [k][v][h]
__device__ float g_c1[HDIM];
__device__ float g_c2[HDIM];
__device__ float g_W2k[3 * HDIM * HDIM];            // [tap][h][h'] tf32-rounded, K-major
__device__ float g_y1t[(size_t)BDIM * PPAD * HDIM]; // [b][p+1][h'] tf32-rounded, halo rows zero
__device__ float g_y2[(size_t)BDIM * HDIM * PDIM];  // [b][h][p]
__device__ int   g_fidx[BDIM * MAXF];

// ---------------- PTX helpers (base ISA only) ----------------
__device__ __forceinline__ uint32_t smem_u32(const void* p) {
    uint32_t a;
    asm("{ .reg .u64 t; cvta.to.shared.u64 t, %1; cvt.u32.u64 %0, t; }" : "=r"(a) : "l"(p));
    return a;
}
__device__ __forceinline__ uint32_t f2tf32(float v) {
    uint32_t t;
    asm("cvt.rna.tf32.f32 %0, %1;" : "=r"(t) : "f"(v));
    return t;
}
__device__ __forceinline__ void cp_async16(uint32_t s, const void* g) {
    asm volatile("cp.async.cg.shared.global [%0], [%1], 16;" :: "r"(s), "l"(g) : "memory");
}
#define CP_COMMIT() asm volatile("cp.async.commit_group;" ::: "memory")
#define CP_WAIT1()  asm volatile("cp.async.wait_group 1;" ::: "memory")

#define LDSM_X4(r0, r1, r2, r3, addr)                                        \
    asm volatile("ldmatrix.sync.aligned.m8n8.x4.shared.b16 {%0,%1,%2,%3}, [%4];" \
        : "=r"(r0), "=r"(r1), "=r"(r2), "=r"(r3) : "r"(addr))

__device__ __forceinline__ void mma1688(float* d, uint32_t a0, uint32_t a1,
                                        uint32_t a2, uint32_t a3,
                                        uint32_t b0, uint32_t b1) {
    asm volatile(
        "mma.sync.aligned.m16n8k8.row.col.f32.tf32.tf32.f32 "
        "{%0,%1,%2,%3}, {%4,%5,%6,%7}, {%8,%9}, {%0,%1,%2,%3};"
        : "+f"(d[0]), "+f"(d[1]), "+f"(d[2]), "+f"(d[3])
        : "r"(a0), "r"(a1), "r"(a2), "r"(a3), "r"(b0), "r"(b1));
}

__device__ __forceinline__ uint32_t sw128(uint32_t off) { return off ^ ((off >> 3) & 0x70); }

// ---------------- prep: fold BN into bias vectors ----------------
__global__ void k_prep_vec(const float* b1, const float* g1, const float* be1,
                           const float* m1, const float* v1,
                           const float* b2, const float* g2, const float* be2,
                           const float* m2, const float* v2) {
    int h = threadIdx.x;
    if (h < HDIM) {
        float s1 = g1[h] * rsqrtf(v1[h] + EPSV);
        g_c1[h] = b1[h] * s1 + be1[h] - m1[h] * s1;
        float s2 = g2[h] * rsqrtf(v2[h] + EPSV);
        g_c2[h] = b2[h] * s2 + be2[h] - m2[h] * s2;
    }
}

// ---------------- prep: transpose conv1_w (H,E,3) -> [k][e][h] ----------------
__global__ void k_w1t(const float* __restrict__ w1) {
    int idx = blockIdx.x * blockDim.x + threadIdx.x;
    if (idx >= 3 * EDIM * HDIM) return;
    int h = idx / (EDIM * 3);
    int r = idx % (EDIM * 3);
    int e = r / 3;
    int k = r % 3;
    g_W1t[(k * EDIM + e) * HDIM + h] = w1[idx];
}

// ---------------- prep: Atab[k][v][h] = scale1[h]*(emb[v] . W1[h,:,k]) ----------------
__global__ void k_atab(const float* __restrict__ emb,
                       const float* __restrict__ g1, const float* __restrict__ v1) {
    int v = blockIdx.x;
    int k = blockIdx.y;
    int h = threadIdx.x;
    __shared__ float es[EDIM];
    es[h] = emb[v * EDIM + h];
    __syncthreads();
    const float* w = g_W1t + (size_t)k * EDIM * HDIM + h;
    float acc = 0.f;
#pragma unroll 8
    for (int e = 0; e < EDIM; ++e)
        acc += es[e] * w[(size_t)e * HDIM];
    float scale = g1[h] * rsqrtf(v1[h] + EPSV);
    g_Atab[((size_t)k * VDIM + v) * HDIM + h] = acc * scale;
}

// ---------------- prep: W2k[tap][h][h'] = tf32(scale2[h]*W2[h,h',tap]) ----------------
__global__ void k_w2k(const float* __restrict__ w2,
                      const float* __restrict__ g2, const float* __restrict__ v2) {
    int idx = blockIdx.x * blockDim.x + threadIdx.x;
    if (idx >= 3 * HDIM * HDIM) return;
    int tap = idx / (HDIM * HDIM);
    int r = idx % (HDIM * HDIM);
    int h = r / HDIM;
    int hp = r % HDIM;
    float s2 = g2[h] * rsqrtf(v2[h] + EPSV);
    float val = w2[h * HDIM * 3 + hp * 3 + tap] * s2;
    ((uint32_t*)g_W2k)[idx] = f2tf32(val);
}

// ---------------- zero halo rows of y1t ----------------
__global__ void k_zhalo() {
    int i = blockIdx.x * blockDim.x + threadIdx.x;
    if (i >= BDIM * 2 * HDIM) return;
    int b = i / (2 * HDIM);
    int r = i % (2 * HDIM);
    int p = (r < HDIM) ? 0 : (PPAD - 1);
    int h = r % HDIM;
    g_y1t[((size_t)b * PPAD + p) * HDIM + h] = 0.f;
}

// ---------------- stage 1: y1 via table lookups -> transposed, padded, tf32 ----------------
__global__ void k_y1(const int* __restrict__ ids) {
    __shared__ int sid[18];
    int b = blockIdx.x;
    int p0 = blockIdx.y * 16;
    int tid = threadIdx.x;   // 256
    if (tid < 18) {
        int q = p0 - 1 + tid;
        sid[tid] = (q >= 0 && q < PDIM) ? ids[b * PDIM + q] : -1;
    }
    __syncthreads();
    uint32_t* out = (uint32_t*)g_y1t;
    for (int h = tid; h < HDIM; h += 256) {
        float cc = g_c1[h];
#pragma unroll
        for (int pl = 0; pl < 16; ++pl) {
            int i0 = sid[pl], i1 = sid[pl + 1], i2 = sid[pl + 2];
            float v = cc;
            if (i0 >= 0) v += g_Atab[(0 * VDIM + i0) * HDIM + h];
            if (i1 >= 0) v += g_Atab[(1 * VDIM + i1) * HDIM + h];
            if (i2 >= 0) v += g_Atab[(2 * VDIM + i2) * HDIM + h];
            v = fmaxf(v, 0.f);
            out[((size_t)b * PPAD + p0 + pl + 1) * HDIM + h] = f2tf32(v);
        }
    }
}

// ---------------- stage 2: conv2 GEMM via mma.sync tf32 ----------------
__global__ __launch_bounds__(256, 2) void k_gemm() {
    extern __shared__ __align__(1024) char smem[];
    uint32_t sb = smem_u32(smem);
    int tid = threadIdx.x;
    int lane = tid & 31, wid = tid >> 5;
    int wm = wid & 1;          // 2 m-tiles of 64
    int wn = wid >> 1;         // 4 n-tiles of 32
    int p0 = blockIdx.x * TN;
    int h0 = blockIdx.y * TM;
    int b = blockIdx.z;

    // ---- per-lane ldmatrix address components (K-major SW128 tiles) ----
    uint32_t aBase[4], aXor[4];
#pragma unroll
    for (int fi = 0; fi < 4; ++fi) {
        int row = wm * 64 + fi * 16 + (lane & 15);
        aBase[fi] = row * 128;
        aXor[fi] = (row & 7) * 16;
    }
    uint32_t aK0 = (lane >> 4) * 16;

    int nb = (lane & 7) | ((lane & 16) >> 1);
    uint32_t bK0 = ((lane >> 3) & 1) * 16;
    uint32_t bBase[2], bXor[2];
#pragma unroll
    for (int half = 0; half < 2; ++half) {
        int row = wn * 32 + half * 16 + nb;
        bBase[half] = row * 128;
        bXor[half] = (row & 7) * 16;
    }

    // ---- stage loader: A 128 rows x 128B + B 128 rows x 128B ----
    auto load_stage = [&](int c, int s) {
        int tap = c >> 4;
        int kk = (c & 15) * TK;
        uint32_t st = sb + s * STAGE_BYTES;
#pragma unroll
        for (int j = 0; j < 8; ++j) {
            int i = tid + j * 256;
            int row = (i >> 3) & 127;
            int seg = i & 7;
            uint32_t off = sw128((uint32_t)(row * 128 + seg * 16));
            if (i < 1024) {
                const float* g = g_W2k + ((size_t)tap * HDIM + h0 + row) * HDIM + kk + seg * 4;
                cp_async16(st + off, g);
            } else {
                const float* g = g_y1t + ((size_t)b * PPAD + p0 + row + tap) * HDIM + kk + seg * 4;
                cp_async16(st + A_BYTES + off, g);
            }
        }
    };

    float acc[4][4][4];
#pragma unroll
    for (int fi = 0; fi < 4; ++fi)
#pragma unroll
        for (int ni = 0; ni < 4; ++ni)
#pragma unroll
            for (int q = 0; q < 4; ++q) acc[fi][ni][q] = 0.f;

    // prologue: stages 0,1
    load_stage(0, 0); CP_COMMIT();
    load_stage(1, 1); CP_COMMIT();

    for (int c = 0; c < NCHUNK; ++c) {
        CP_WAIT1();
        __syncthreads();
        if (c + 2 < NCHUNK) load_stage(c + 2, (c + 2) % NSTAGE);
        CP_COMMIT();

        uint32_t stA = sb + (c % NSTAGE) * STAGE_BYTES;
        uint32_t stB = stA + A_BYTES;
#pragma unroll
        for (int j = 0; j < 4; ++j) {
            uint32_t a[4][4], bf[2][4];
#pragma unroll
            for (int fi = 0; fi < 4; ++fi) {
                uint32_t addr = stA + aBase[fi] + ((aK0 + j * 32) ^ aXor[fi]);
                LDSM_X4(a[fi][0], a[fi][1], a[fi][2], a[fi][3], addr);
            }
#pragma unroll
            for (int half = 0; half < 2; ++half) {
                uint32_t addr = stB + bBase[half] + ((bK0 + j * 32) ^ bXor[half]);
                LDSM_X4(bf[half][0], bf[half][1], bf[half][2], bf[half][3], addr);
            }
#pragma unroll
            for (int fi = 0; fi < 4; ++fi)
#pragma unroll
                for (int ni = 0; ni < 4; ++ni)
                    mma1688(acc[fi][ni], a[fi][0], a[fi][1], a[fi][2], a[fi][3],
                            bf[ni >> 1][(ni & 1) * 2], bf[ni >> 1][(ni & 1) * 2 + 1]);
        }
    }

    // ---- epilogue: bias + relu, direct store to y2[b][h][p] ----
    int hr = h0 + wm * 64 + (lane >> 2);
    int pc = p0 + wn * 32 + (lane & 3) * 2;
#pragma unroll
    for (int fi = 0; fi < 4; ++fi) {
        int h = hr + fi * 16;
        float c0 = g_c2[h];
        float c1 = g_c2[h + 8];
        float* base0 = g_y2 + ((size_t)b * HDIM + h) * PDIM;
        float* base1 = base0 + 8 * PDIM;
#pragma unroll
        for (int ni = 0; ni < 4; ++ni) {
            int p = pc + ni * 8;
            float2 v0, v1;
            v0.x = fmaxf(acc[fi][ni][0] + c0, 0.f);
            v0.y = fmaxf(acc[fi][ni][1] + c0, 0.f);
            v1.x = fmaxf(acc[fi][ni][2] + c1, 0.f);
            v1.y = fmaxf(acc[fi][ni][3] + c1, 0.f);
            *(float2*)(base0 + p) = v0;
            *(float2*)(base1 + p) = v1;
        }
    }
}

// ---------------- stage 3: duration scan + frame->phoneme map ----------------
__global__ void k_scan(const int* __restrict__ durs, int F) {
    int b = blockIdx.x;
    int tid = threadIdx.x;   // 1024
    __shared__ int s[PDIM];
    int d = durs[b * PDIM + tid];
    s[tid] = d;
    __syncthreads();
    for (int off = 1; off < PDIM; off <<= 1) {
        int t = (tid >= off) ? s[tid - off] : 0;
        __syncthreads();
        s[tid] += t;
        __syncthreads();
    }
    int cum = s[tid];
    int total = s[PDIM - 1];
    int start = cum - d;
    for (int f = start; f < cum; ++f) g_fidx[b * MAXF + f] = tid;
    for (int f = total + tid; f < F; f += PDIM) g_fidx[b * MAXF + f] = -1;
}

// ---------------- stage 4: gather + mask ----------------
__global__ void k_gather(float* __restrict__ out, int F) {
    int bh = blockIdx.x;
    int b = bh / HDIM;
    const float* row = g_y2 + (size_t)bh * PDIM;
    const int* fx = g_fidx + b * MAXF;
    float* o = out + (size_t)bh * F;
    for (int f = threadIdx.x; f < F; f += blockDim.x) {
        int ix = fx[f];
        o[f] = (ix >= 0) ? row[ix] : 0.f;
    }
}

// ---------------- launch ----------------
extern "C" void kernel_launch(void* const* d_in, const int* in_sizes, int n_in,
                              void* d_out, int out_size) {
    const int* ids   = (const int*)d_in[0];
    const int* durs  = (const int*)d_in[1];
    const float* emb = (const float*)d_in[2];
    const float* w1  = (const float*)d_in[3];
    const float* b1  = (const float*)d_in[4];
    const float* g1  = (const float*)d_in[5];
    const float* be1 = (const float*)d_in[6];
    const float* m1  = (const float*)d_in[7];
    const float* v1  = (const float*)d_in[8];
    const float* w2  = (const float*)d_in[9];
    const float* b2  = (const float*)d_in[10];
    const float* g2  = (const float*)d_in[11];
    const float* be2 = (const float*)d_in[12];
    const float* m2  = (const float*)d_in[13];
    const float* v2  = (const float*)d_in[14];
    float* out = (float*)d_out;
    int F = out_size / (BDIM * HDIM);

    cudaFuncSetAttribute(k_gemm, cudaFuncAttributeMaxDynamicSharedMemorySize, GEMM_SMEM);

    k_prep_vec<<<1, 512>>>(b1, g1, be1, m1, v1, b2, g2, be2, m2, v2);
    k_w1t<<<(3 * EDIM * HDIM + 255) / 256, 256>>>(w1);
    k_atab<<<dim3(VDIM, 3), 512>>>(emb, g1, v1);
    k_w2k<<<(3 * HDIM * HDIM + 255) / 256, 256>>>(w2, g2, v2);
    k_zhalo<<<(BDIM * 2 * HDIM + 255) / 256, 256>>>();
    k_y1<<<dim3(BDIM, PDIM / 16), 256>>>(ids);
    k_gemm<<<dim3(PDIM / TN, HDIM / TM, BDIM), 256, GEMM_SMEM>>>();
    k_scan<<<BDIM, PDIM>>>(durs, F);
    k_gather<<<BDIM * HDIM, 256>>>(out, F);
}